// round 7
// baseline (speedup 1.0000x reference)
#include <cuda_runtime.h>
#include <math.h>

// Problem constants (fixed by the dataset)
#define Bsz 1024
#define Tn  200
#define LXn 190
#define LYn 50
#define Hd  256
#define XDd 64
#define YDd 64

#define GRID 128
#define NTHR 256
#define ROWS 8

typedef unsigned long long ull;

// ---------------- per-CTA activation scratch in GLOBAL memory ----------------
// Activations are read with uniform-address LDG.128 (1 wavefront, L1-dedup'd
// broadcast) instead of smem LDS.128 (4 wavefronts each). Layout per CTA
// (floats), every buffer is [cols][8 rows] transposed:
//   A   0      : [576][8]  cat(hi, s, x)
//   C   4608   : [576][8]  cat(c1, c2, x)
//   H   9216   : [256][8]
//   S   11264  : [256][8]
//   TF  13312  : [256][8]
//   TU  15360  : [256][8]
//   TR  17408  : [256][8]
//   TN  19456  : [256][8]
//   U   21504  : [256][8]
#define OFF_A  0
#define OFF_C  4608
#define OFF_H  9216
#define OFF_S  11264
#define OFF_TF 13312
#define OFF_TU 15360
#define OFF_TR 17408
#define OFF_TN 19456
#define OFF_U  21504
#define ACT_FLOATS 23552

__device__ float g_act[(size_t)GRID * ACT_FLOATS];
__device__ float g_ybT[(size_t)LYn * GRID * Hd * ROWS]; // saved new_y: [q][cta][col][8]
__device__ float g_dt[Tn];
__device__ int   g_obs[Tn];
__device__ int   g_qm [Tn];

// ---------------- packed f32x2 helpers ---------------------------------------
__device__ __forceinline__ ull fma2(ull a, ull b, ull c) {
    ull d;
    asm("fma.rn.f32x2 %0, %1, %2, %3;" : "=l"(d) : "l"(a), "l"(b), "l"(c));
    return d;
}
__device__ __forceinline__ ull dup2(float x) {
    ull d;
    asm("mov.b64 %0, {%1, %1};" : "=l"(d) : "f"(x));
    return d;
}
__device__ __forceinline__ void unpk(ull u, float& lo, float& hi) {
    asm("mov.b64 {%0, %1}, %2;" : "=f"(lo), "=f"(hi) : "l"(u));
}

__device__ __forceinline__ float sigm(float x) {
    return __fdividef(1.0f, 1.0f + __expf(-x));
}
__device__ __forceinline__ float tanh_f(float x) {
    // tanh(x) = 2*sigmoid(2x) - 1 ; |err| ~1e-6, far within 1e-3 budget
    return fmaf(2.0f, sigm(2.0f*x), -1.0f);
}

__device__ __forceinline__ void store8(float* p, const float v[8]) {
    *(float4*)p       = make_float4(v[0], v[1], v[2], v[3]);
    *(float4*)(p + 4) = make_float4(v[4], v[5], v[6], v[7]);
}

// ---------------- GEMM cores --------------------------------------------------
// A: GLOBAL activation buffer [k][8 rows], stride 8 floats. Uniform address
// across the warp -> 1 L1 wavefront per LDG.128. Weights via __ldcg (L2-only,
// keeps L1 free for activations). K must be a multiple of 32 (gemm1) / 16 (gemm2).
__device__ __forceinline__ void gemm1(const float* A, int K,
                                      const float* __restrict__ Wc, int ldw,
                                      float v[8])
{
    ull a0 = 0, a1 = 0, a2 = 0, a3 = 0;
    float w0[16], w1[16];
#pragma unroll
    for (int p = 0; p < 16; p++) w0[p] = __ldcg(Wc + (size_t)p*ldw);

    for (int kb = 0; kb < K; kb += 32) {
        // prefetch second half of this 32-block
#pragma unroll
        for (int p = 0; p < 16; p++) w1[p] = __ldcg(Wc + (size_t)(kb + 16 + p)*ldw);
#pragma unroll
        for (int kk = 0; kk < 16; kk++) {
            const float* ap = A + (kb + kk)*8;
            ulonglong2 A0 = *(const ulonglong2*)ap;
            ulonglong2 A1 = *(const ulonglong2*)(ap + 4);
            ull wb = dup2(w0[kk]);
            a0 = fma2(A0.x, wb, a0);
            a1 = fma2(A0.y, wb, a1);
            a2 = fma2(A1.x, wb, a2);
            a3 = fma2(A1.y, wb, a3);
        }
        if (kb + 32 < K) {
#pragma unroll
            for (int p = 0; p < 16; p++) w0[p] = __ldcg(Wc + (size_t)(kb + 32 + p)*ldw);
        }
#pragma unroll
        for (int kk = 0; kk < 16; kk++) {
            const float* ap = A + (kb + 16 + kk)*8;
            ulonglong2 A0 = *(const ulonglong2*)ap;
            ulonglong2 A1 = *(const ulonglong2*)(ap + 4);
            ull wb = dup2(w1[kk]);
            a0 = fma2(A0.x, wb, a0);
            a1 = fma2(A0.y, wb, a1);
            a2 = fma2(A1.x, wb, a2);
            a3 = fma2(A1.y, wb, a3);
        }
    }
    unpk(a0, v[0], v[1]);
    unpk(a1, v[2], v[3]);
    unpk(a2, v[4], v[5]);
    unpk(a3, v[6], v[7]);
}

// Two output columns sharing the same A stream.
__device__ __forceinline__ void gemm2(const float* A, int K,
                                      const float* __restrict__ Wa,
                                      const float* __restrict__ Wb, int ldw,
                                      float va[8], float vb[8])
{
    ull a0 = 0, a1 = 0, a2 = 0, a3 = 0;
    ull b0 = 0, b1 = 0, b2 = 0, b3 = 0;
    float wa0[8], wa1[8], wb0[8], wb1[8];
#pragma unroll
    for (int p = 0; p < 8; p++) {
        wa0[p] = __ldcg(Wa + (size_t)p*ldw);
        wb0[p] = __ldcg(Wb + (size_t)p*ldw);
    }
    for (int kb = 0; kb < K; kb += 16) {
#pragma unroll
        for (int p = 0; p < 8; p++) {
            wa1[p] = __ldcg(Wa + (size_t)(kb + 8 + p)*ldw);
            wb1[p] = __ldcg(Wb + (size_t)(kb + 8 + p)*ldw);
        }
#pragma unroll
        for (int kk = 0; kk < 8; kk++) {
            const float* ap = A + (kb + kk)*8;
            ulonglong2 A0 = *(const ulonglong2*)ap;
            ulonglong2 A1 = *(const ulonglong2*)(ap + 4);
            ull wA = dup2(wa0[kk]);
            ull wB = dup2(wb0[kk]);
            a0 = fma2(A0.x, wA, a0); b0 = fma2(A0.x, wB, b0);
            a1 = fma2(A0.y, wA, a1); b1 = fma2(A0.y, wB, b1);
            a2 = fma2(A1.x, wA, a2); b2 = fma2(A1.x, wB, b2);
            a3 = fma2(A1.y, wA, a3); b3 = fma2(A1.y, wB, b3);
        }
        if (kb + 16 < K) {
#pragma unroll
            for (int p = 0; p < 8; p++) {
                wa0[p] = __ldcg(Wa + (size_t)(kb + 16 + p)*ldw);
                wb0[p] = __ldcg(Wb + (size_t)(kb + 16 + p)*ldw);
            }
        }
#pragma unroll
        for (int kk = 0; kk < 8; kk++) {
            const float* ap = A + (kb + 8 + kk)*8;
            ulonglong2 A0 = *(const ulonglong2*)ap;
            ulonglong2 A1 = *(const ulonglong2*)(ap + 4);
            ull wA = dup2(wa1[kk]);
            ull wB = dup2(wb1[kk]);
            a0 = fma2(A0.x, wA, a0); b0 = fma2(A0.x, wB, b0);
            a1 = fma2(A0.y, wA, a1); b1 = fma2(A0.y, wB, b1);
            a2 = fma2(A1.x, wA, a2); b2 = fma2(A1.x, wB, b2);
            a3 = fma2(A1.y, wA, a3); b3 = fma2(A1.y, wB, b3);
        }
    }
    unpk(a0, va[0], va[1]); unpk(b0, vb[0], vb[1]);
    unpk(a1, va[2], va[3]); unpk(b1, vb[2], vb[3]);
    unpk(a2, va[4], va[5]); unpk(b2, vb[4], vb[5]);
    unpk(a3, va[6], va[7]); unpk(b3, vb[6], vb[7]);
}

// ---------------- init: dt / obs-slot / query maps ---------------------------
__global__ void init_kernel(const float* __restrict__ x_time,
                            const int* __restrict__ x_idx,
                            const int* __restrict__ y_idx) {
    int tid = threadIdx.x;
    for (int t = tid; t < Tn; t += blockDim.x) { g_obs[t] = -1; g_qm[t] = -1; }
    __syncthreads();
    for (int i = tid; i < LXn; i += blockDim.x) g_obs[x_idx[i]] = i;
    for (int j = tid; j < LYn; j += blockDim.x) g_qm[y_idx[j]] = j;
    __syncthreads();
    for (int t = tid; t < Tn; t += blockDim.x) {
        float d;
        float tlast = x_time[Tn - 1];
        if (t == 0)      d = tlast - (tlast + 0.01f);   // ti - prev_ti at step 0
        else if (t == 1) d = tlast - x_time[0];
        else             d = x_time[t - 2] - x_time[t - 1];
        g_dt[t] = d;
    }
}

// ---------------- persistent per-CTA recurrence -------------------------------
__global__ void __launch_bounds__(NTHR, 1)
recur_kernel(const float* __restrict__ xd, const float* __restrict__ xm,
             const float* __restrict__ ug_w1, const float* __restrict__ ug_b1,
             const float* __restrict__ ug_w2, const float* __restrict__ ug_b2,
             const float* __restrict__ rg_w1, const float* __restrict__ rg_b1,
             const float* __restrict__ rg_w2, const float* __restrict__ rg_b2,
             const float* __restrict__ ns_w1, const float* __restrict__ ns_b1,
             const float* __restrict__ ns_w2, const float* __restrict__ ns_b2,
             const float* __restrict__ out_w1, const float* __restrict__ out_b1,
             const float* __restrict__ out_w2, const float* __restrict__ out_b2,
             const float* __restrict__ f_w1, const float* __restrict__ f_b1,
             const float* __restrict__ f_w2, const float* __restrict__ f_b2,
             float* __restrict__ out)
{
    const int tid = threadIdx.x;
    const int cta = blockIdx.x;
    const int m0  = cta * ROWS;

    float* base = g_act + (size_t)cta * ACT_FLOATS;
    float* gA  = base + OFF_A;
    float* gC  = base + OFF_C;
    float* gH  = base + OFF_H;
    float* gS  = base + OFF_S;
    float* gTF = base + OFF_TF;
    float* gTU = base + OFF_TU;
    float* gTR = base + OFF_TR;
    float* gTN = base + OFF_TN;
    float* gU  = base + OFF_U;

    // zero h, s
    for (int i = tid; i < 2048; i += NTHR) { gH[i] = 0.0f; gS[i] = 0.0f; }
    __syncthreads();

    float v[8];

    for (int t = 0; t < Tn; t++) {
        const int   obs = g_obs[t];
        const int   q   = g_qm[t];
        const float dt  = g_dt[t];

        // ---- step prologue: s -> A[256:512]; x -> A/C[512:576] ----
        {
            float4 s0 = *(float4*)&gS[tid*8];
            float4 s1 = *(float4*)&gS[tid*8 + 4];
            *(float4*)&gA[(256 + tid)*8]     = s0;
            *(float4*)&gA[(256 + tid)*8 + 4] = s1;
        }
        if (tid < XDd) {
            float xv[8];
            if (obs >= 0) {
#pragma unroll
                for (int r = 0; r < 8; r++) {
                    int off = ((m0 + r)*LXn + obs)*XDd + tid;
                    xv[r] = __ldg(xd + off) * __ldg(xm + off);
                }
            } else {
#pragma unroll
                for (int r = 0; r < 8; r++) xv[r] = 0.0f;
            }
            store8(&gA[(512 + tid)*8], xv);
            store8(&gC[(512 + tid)*8], xv);
        }
        __syncthreads();

        // ---- S1: tf = tanh(h @ f_w1 + b1) ----
        gemm1(gH, 256, f_w1 + tid, Hd, v);
        {
            float b = __ldg(f_b1 + tid);
#pragma unroll
            for (int r = 0; r < 8; r++) v[r] = tanh_f(v[r] + b);
            store8(&gTF[tid*8], v);
        }
        __syncthreads();

        // ---- S2: hi = h + dt*(tf @ f_w2 + b2) -> A[0:256] ----
        gemm1(gTF, 256, f_w2 + tid, Hd, v);
        {
            float b = __ldg(f_b2 + tid);
#pragma unroll
            for (int r = 0; r < 8; r++) v[r] = gH[tid*8 + r] + dt*(v[r] + b);
            store8(&gA[tid*8], v);
        }
        __syncthreads();

        // ---- S3 (fused): tu = tanh(cat@ug_w1+b), tr = tanh(cat@rg_w1+b) ----
        {
            float vb_[8];
            gemm2(gA, 576, ug_w1 + tid, rg_w1 + tid, Hd, v, vb_);
            float bu = __ldg(ug_b1 + tid), br = __ldg(rg_b1 + tid);
#pragma unroll
            for (int r = 0; r < 8; r++) {
                v[r]   = tanh_f(v[r] + bu);
                vb_[r] = tanh_f(vb_[r] + br);
            }
            store8(&gTU[tid*8], v);
            store8(&gTR[tid*8], vb_);
        }
        __syncthreads();

        // ---- S4a: u = sigmoid(tu @ ug_w2 + b) ----
        gemm1(gTU, 256, ug_w2 + tid, Hd, v);
        {
            float b = __ldg(ug_b2 + tid);
#pragma unroll
            for (int r = 0; r < 8; r++) v[r] = sigm(v[r] + b);
            store8(&gU[tid*8], v);
        }
        // (no sync: S4b reads gTR / writes gC — disjoint from S4a)

        // ---- S4b: r = sigmoid(tr @ rg_w2 + b); c1 = hi*r, c2 = s*r ----
        gemm1(gTR, 256, rg_w2 + tid, Hd, v);
        {
            float b = __ldg(rg_b2 + tid);
            float c1[8], c2[8];
#pragma unroll
            for (int r = 0; r < 8; r++) {
                float rr = sigm(v[r] + b);
                c1[r] = gA[tid*8 + r] * rr;
                c2[r] = gA[(256 + tid)*8 + r] * rr;
            }
            store8(&gC[tid*8], c1);
            store8(&gC[(256 + tid)*8], c2);
        }
        __syncthreads();

        // ---- S5: tn = tanh(cc @ ns_w1 + b) ----
        gemm1(gC, 576, ns_w1 + tid, Hd, v);
        {
            float b = __ldg(ns_b1 + tid);
#pragma unroll
            for (int r = 0; r < 8; r++) v[r] = tanh_f(v[r] + b);
            store8(&gTN[tid*8], v);
        }
        __syncthreads();

        // ---- S6 (fused N=512): ns | ns_std, gated state update ----
        {
            float vs[8];
            gemm2(gTN, 256, ns_w2 + tid, ns_w2 + tid + Hd, 2*Hd, v, vs);
            float b1_ = __ldg(ns_b2 + tid), b2_ = __ldg(ns_b2 + tid + Hd);
            float hy[8], sy[8];
#pragma unroll
            for (int r = 0; r < 8; r++) {
                float u_  = gU[tid*8 + r];
                float hi_ = gA[tid*8 + r];
                float so_ = gA[(256 + tid)*8 + r];
                float ns_ = v[r] + b1_;
                float sd_ = fabsf(vs[r] + b2_);
                hy[r] = (1.0f - u_)*ns_ + u_*hi_;
                sy[r] = fabsf((1.0f - u_)*sd_ + u_*so_);
            }
            store8(&gH[tid*8], hy);
            store8(&gS[tid*8], sy);
            if (q >= 0) {
                float* d = g_ybT + (((size_t)q*GRID + cta)*Hd + tid)*8;
                store8(d, hy);
            }
        }
        __syncthreads();
    }

    // ---- deferred out-MLP: per-CTA, 50 query states (yb already in A-layout) ----
    for (int q = 0; q < LYn; q++) {
        const float* ybq = g_ybT + ((size_t)q*GRID + cta)*Hd*8;

        gemm1(ybq, 256, out_w1 + tid, Hd, v);
        {
            float b = __ldg(out_b1 + tid);
#pragma unroll
            for (int r = 0; r < 8; r++) v[r] = tanh_f(v[r] + b);
            store8(&gTF[tid*8], v);
        }
        __syncthreads();

        if (tid < YDd) {
            gemm1(gTF, 256, out_w2 + tid, YDd, v);
            float b = __ldg(out_b2 + tid);
#pragma unroll
            for (int r = 0; r < 8; r++)
                out[((size_t)(m0 + r)*LYn + q)*YDd + tid] = v[r] + b;
        }
        __syncthreads();
    }
}

// ---------------- launch ------------------------------------------------------
extern "C" void kernel_launch(void* const* d_in, const int* in_sizes, int n_in,
                              void* d_out, int out_size) {
    (void)in_sizes; (void)n_in; (void)out_size;
    const float* xd  = (const float*)d_in[0];
    const float* xm  = (const float*)d_in[1];
    const float* xt  = (const float*)d_in[2];
    const int*   xti = (const int*)d_in[3];
    const int*   yti = (const int*)d_in[4];

    init_kernel<<<1, 256>>>(xt, xti, yti);

    recur_kernel<<<GRID, NTHR>>>(
        xd, xm,
        (const float*)d_in[5],  (const float*)d_in[6],  (const float*)d_in[7],  (const float*)d_in[8],
        (const float*)d_in[9],  (const float*)d_in[10], (const float*)d_in[11], (const float*)d_in[12],
        (const float*)d_in[13], (const float*)d_in[14], (const float*)d_in[15], (const float*)d_in[16],
        (const float*)d_in[17], (const float*)d_in[18], (const float*)d_in[19], (const float*)d_in[20],
        (const float*)d_in[21], (const float*)d_in[22], (const float*)d_in[23], (const float*)d_in[24],
        (float*)d_out);
}

// round 8
// speedup vs baseline: 2.0476x; 2.0476x over previous
#include <cuda_runtime.h>
#include <math.h>

// Problem constants (fixed by the dataset)
#define Bsz 1024
#define Tn  200
#define LXn 190
#define LYn 50
#define Hd  256
#define XDd 64
#define YDd 64

#define GRID 128
#define NTHR 256
#define ROWS 8
#define PHALF 4096   // floats per k-half partial buffer (512 cols x 8 rows)

typedef unsigned long long ull;

// ---------------- device scratch ---------------------------------------------
__device__ float g_ybT[(size_t)LYn*GRID*Hd*ROWS];   // saved new_y: [q][cta][col][8]
__device__ float g_dt[Tn];
__device__ int   g_obs[Tn];
__device__ int   g_qm [Tn];

// ---------------- packed f32x2 helpers ---------------------------------------
__device__ __forceinline__ ull fma2(ull a, ull b, ull c) {
    ull d;
    asm("fma.rn.f32x2 %0, %1, %2, %3;" : "=l"(d) : "l"(a), "l"(b), "l"(c));
    return d;
}
__device__ __forceinline__ ull dup2(float x) {
    ull d;
    asm("mov.b64 %0, {%1, %1};" : "=l"(d) : "f"(x));
    return d;
}
__device__ __forceinline__ void unpk(ull u, float& lo, float& hi) {
    asm("mov.b64 {%0, %1}, %2;" : "=f"(lo), "=f"(hi) : "l"(u));
}

__device__ __forceinline__ float sigm(float x) {
    return __fdividef(1.0f, 1.0f + __expf(-x));
}
__device__ __forceinline__ float tanh_f(float x) {
    return fmaf(2.0f, sigm(2.0f*x), -1.0f);   // |err| ~1e-6 << 1e-3 budget
}

__device__ __forceinline__ void store8(float* p, const float v[8]) {
    *(float4*)p       = make_float4(v[0], v[1], v[2], v[3]);
    *(float4*)(p + 4) = make_float4(v[4], v[5], v[6], v[7]);
}

// ---------------- GEMM cores --------------------------------------------------
// A operand lives in smem, layout [k][8 rows] (stride 8 floats), broadcast LDS.
// Each thread accumulates over k in [k0, k0+Kh).
//
// gemmA: 2 adjacent output columns (weights as float2).  Kh % 16 == 0.
// acc[0..3] = col c rows(0..7 as f32x2), acc[4..7] = col c+1.
__device__ __forceinline__ void gemmA(const float* As, int k0, int Kh,
                                      const float* __restrict__ W2, int ldw,
                                      ull acc[8])
{
#pragma unroll
    for (int i = 0; i < 8; i++) acc[i] = 0ULL;
    float2 w0[8], w1[8];
#pragma unroll
    for (int p = 0; p < 8; p++) w0[p] = __ldg((const float2*)(W2 + (size_t)(k0 + p)*ldw));

    for (int kb = k0; kb < k0 + Kh; kb += 16) {
#pragma unroll
        for (int p = 0; p < 8; p++) w1[p] = __ldg((const float2*)(W2 + (size_t)(kb + 8 + p)*ldw));
#pragma unroll
        for (int kk = 0; kk < 8; kk++) {
            const float* ap = As + (kb + kk)*8;
            ulonglong2 A0 = *(const ulonglong2*)ap;
            ulonglong2 A1 = *(const ulonglong2*)(ap + 4);
            ull wx = dup2(w0[kk].x), wy = dup2(w0[kk].y);
            acc[0] = fma2(A0.x, wx, acc[0]); acc[1] = fma2(A0.y, wx, acc[1]);
            acc[2] = fma2(A1.x, wx, acc[2]); acc[3] = fma2(A1.y, wx, acc[3]);
            acc[4] = fma2(A0.x, wy, acc[4]); acc[5] = fma2(A0.y, wy, acc[5]);
            acc[6] = fma2(A1.x, wy, acc[6]); acc[7] = fma2(A1.y, wy, acc[7]);
        }
        if (kb + 16 < k0 + Kh) {
#pragma unroll
            for (int p = 0; p < 8; p++) w0[p] = __ldg((const float2*)(W2 + (size_t)(kb + 16 + p)*ldw));
        }
#pragma unroll
        for (int kk = 0; kk < 8; kk++) {
            const float* ap = As + (kb + 8 + kk)*8;
            ulonglong2 A0 = *(const ulonglong2*)ap;
            ulonglong2 A1 = *(const ulonglong2*)(ap + 4);
            ull wx = dup2(w1[kk].x), wy = dup2(w1[kk].y);
            acc[0] = fma2(A0.x, wx, acc[0]); acc[1] = fma2(A0.y, wx, acc[1]);
            acc[2] = fma2(A1.x, wx, acc[2]); acc[3] = fma2(A1.y, wx, acc[3]);
            acc[4] = fma2(A0.x, wy, acc[4]); acc[5] = fma2(A0.y, wy, acc[5]);
            acc[6] = fma2(A1.x, wy, acc[6]); acc[7] = fma2(A1.y, wy, acc[7]);
        }
    }
}

// gemmB: 4 adjacent output columns (weights as float4).  Kh % 8 == 0.
// acc[col*4 + rp]
__device__ __forceinline__ void gemmB(const float* As, int k0, int Kh,
                                      const float* __restrict__ W4, int ldw,
                                      ull acc[16])
{
#pragma unroll
    for (int i = 0; i < 16; i++) acc[i] = 0ULL;
    float4 w0[4], w1[4];
#pragma unroll
    for (int p = 0; p < 4; p++) w0[p] = __ldg((const float4*)(W4 + (size_t)(k0 + p)*ldw));

    for (int kb = k0; kb < k0 + Kh; kb += 8) {
#pragma unroll
        for (int p = 0; p < 4; p++) w1[p] = __ldg((const float4*)(W4 + (size_t)(kb + 4 + p)*ldw));
#pragma unroll
        for (int kk = 0; kk < 4; kk++) {
            const float* ap = As + (kb + kk)*8;
            ulonglong2 A0 = *(const ulonglong2*)ap;
            ulonglong2 A1 = *(const ulonglong2*)(ap + 4);
            ull wx = dup2(w0[kk].x), wy = dup2(w0[kk].y);
            ull wz = dup2(w0[kk].z), ww = dup2(w0[kk].w);
            acc[0]  = fma2(A0.x, wx, acc[0]);  acc[1]  = fma2(A0.y, wx, acc[1]);
            acc[2]  = fma2(A1.x, wx, acc[2]);  acc[3]  = fma2(A1.y, wx, acc[3]);
            acc[4]  = fma2(A0.x, wy, acc[4]);  acc[5]  = fma2(A0.y, wy, acc[5]);
            acc[6]  = fma2(A1.x, wy, acc[6]);  acc[7]  = fma2(A1.y, wy, acc[7]);
            acc[8]  = fma2(A0.x, wz, acc[8]);  acc[9]  = fma2(A0.y, wz, acc[9]);
            acc[10] = fma2(A1.x, wz, acc[10]); acc[11] = fma2(A1.y, wz, acc[11]);
            acc[12] = fma2(A0.x, ww, acc[12]); acc[13] = fma2(A0.y, ww, acc[13]);
            acc[14] = fma2(A1.x, ww, acc[14]); acc[15] = fma2(A1.y, ww, acc[15]);
        }
        if (kb + 8 < k0 + Kh) {
#pragma unroll
            for (int p = 0; p < 4; p++) w0[p] = __ldg((const float4*)(W4 + (size_t)(kb + 8 + p)*ldw));
        }
#pragma unroll
        for (int kk = 0; kk < 4; kk++) {
            const float* ap = As + (kb + 4 + kk)*8;
            ulonglong2 A0 = *(const ulonglong2*)ap;
            ulonglong2 A1 = *(const ulonglong2*)(ap + 4);
            ull wx = dup2(w1[kk].x), wy = dup2(w1[kk].y);
            ull wz = dup2(w1[kk].z), ww = dup2(w1[kk].w);
            acc[0]  = fma2(A0.x, wx, acc[0]);  acc[1]  = fma2(A0.y, wx, acc[1]);
            acc[2]  = fma2(A1.x, wx, acc[2]);  acc[3]  = fma2(A1.y, wx, acc[3]);
            acc[4]  = fma2(A0.x, wy, acc[4]);  acc[5]  = fma2(A0.y, wy, acc[5]);
            acc[6]  = fma2(A1.x, wy, acc[6]);  acc[7]  = fma2(A1.y, wy, acc[7]);
            acc[8]  = fma2(A0.x, wz, acc[8]);  acc[9]  = fma2(A0.y, wz, acc[9]);
            acc[10] = fma2(A1.x, wz, acc[10]); acc[11] = fma2(A1.y, wz, acc[11]);
            acc[12] = fma2(A0.x, ww, acc[12]); acc[13] = fma2(A0.y, ww, acc[13]);
            acc[14] = fma2(A1.x, ww, acc[14]); acc[15] = fma2(A1.y, ww, acc[15]);
        }
    }
}

// single-column full-K core (used only for the tiny O2 stage)
__device__ __forceinline__ void gemm1f(const float* As, int K,
                                       const float* __restrict__ Wc, int ldw,
                                       float v[8])
{
    ull a0 = 0, a1 = 0, a2 = 0, a3 = 0;
    for (int k = 0; k < K; k++) {
        const float* ap = As + k*8;
        ulonglong2 A0 = *(const ulonglong2*)ap;
        ulonglong2 A1 = *(const ulonglong2*)(ap + 4);
        ull wb = dup2(__ldg(Wc + (size_t)k*ldw));
        a0 = fma2(A0.x, wb, a0); a1 = fma2(A0.y, wb, a1);
        a2 = fma2(A1.x, wb, a2); a3 = fma2(A1.y, wb, a3);
    }
    unpk(a0, v[0], v[1]); unpk(a1, v[2], v[3]);
    unpk(a2, v[4], v[5]); unpk(a3, v[6], v[7]);
}

// store gemmA partials (2 cols)
__device__ __forceinline__ void stpA(float* sP, int kh, int c, const ull acc[8]) {
    float v0[8], v1[8];
    unpk(acc[0], v0[0], v0[1]); unpk(acc[1], v0[2], v0[3]);
    unpk(acc[2], v0[4], v0[5]); unpk(acc[3], v0[6], v0[7]);
    unpk(acc[4], v1[0], v1[1]); unpk(acc[5], v1[2], v1[3]);
    unpk(acc[6], v1[4], v1[5]); unpk(acc[7], v1[6], v1[7]);
    store8(&sP[kh*PHALF + c*8], v0);
    store8(&sP[kh*PHALF + (c + 1)*8], v1);
}
// store gemmB partials (4 cols)
__device__ __forceinline__ void stpB(float* sP, int kh, int c4, const ull acc[16]) {
#pragma unroll
    for (int cc = 0; cc < 4; cc++) {
        float v[8];
        unpk(acc[cc*4 + 0], v[0], v[1]); unpk(acc[cc*4 + 1], v[2], v[3]);
        unpk(acc[cc*4 + 2], v[4], v[5]); unpk(acc[cc*4 + 3], v[6], v[7]);
        store8(&sP[kh*PHALF + (c4 + cc)*8], v);
    }
}
// epilogue read: combined partial for column col (+optional extra offset)
__device__ __forceinline__ void rdp(const float* sP, int col, int off, float v[8]) {
    const float* p0 = sP + off + col*8;
    const float* p1 = p0 + PHALF;
    float4 a0 = *(const float4*)p0, a1 = *(const float4*)(p0 + 4);
    float4 b0 = *(const float4*)p1, b1 = *(const float4*)(p1 + 4);
    v[0] = a0.x + b0.x; v[1] = a0.y + b0.y; v[2] = a0.z + b0.z; v[3] = a0.w + b0.w;
    v[4] = a1.x + b1.x; v[5] = a1.y + b1.y; v[6] = a1.z + b1.z; v[7] = a1.w + b1.w;
}

// ---------------- init: dt / obs-slot / query maps ---------------------------
__global__ void init_kernel(const float* __restrict__ x_time,
                            const int* __restrict__ x_idx,
                            const int* __restrict__ y_idx) {
    int tid = threadIdx.x;
    for (int t = tid; t < Tn; t += blockDim.x) { g_obs[t] = -1; g_qm[t] = -1; }
    __syncthreads();
    for (int i = tid; i < LXn; i += blockDim.x) g_obs[x_idx[i]] = i;
    for (int j = tid; j < LYn; j += blockDim.x) g_qm[y_idx[j]] = j;
    __syncthreads();
    for (int t = tid; t < Tn; t += blockDim.x) {
        float d;
        float tlast = x_time[Tn - 1];
        if (t == 0)      d = tlast - (tlast + 0.01f);
        else if (t == 1) d = tlast - x_time[0];
        else             d = x_time[t - 2] - x_time[t - 1];
        g_dt[t] = d;
    }
}

// ---------------- smem layout (floats) ----------------------------------------
#define OFF_A  0        // [576][8] cat(hi, s, x)
#define OFF_C  4608     // [576][8] cat(c1, c2, x)
#define OFF_H  9216     // [256][8]
#define OFF_S  11264    // [256][8]
#define OFF_TF 13312    // [256][8]
#define OFF_TU 15360    // [256][8]
#define OFF_TR 17408    // [256][8]
#define OFF_TN 19456    // [256][8]
#define OFF_U  21504    // [256][8]
#define OFF_P  23552    // [2][512][8] partials
#define SMEM_FLOATS 31744

// ---------------- persistent per-CTA recurrence -------------------------------
__global__ void __launch_bounds__(NTHR, 1)
recur_kernel(const float* __restrict__ xd, const float* __restrict__ xm,
             const float* __restrict__ ug_w1, const float* __restrict__ ug_b1,
             const float* __restrict__ ug_w2, const float* __restrict__ ug_b2,
             const float* __restrict__ rg_w1, const float* __restrict__ rg_b1,
             const float* __restrict__ rg_w2, const float* __restrict__ rg_b2,
             const float* __restrict__ ns_w1, const float* __restrict__ ns_b1,
             const float* __restrict__ ns_w2, const float* __restrict__ ns_b2,
             const float* __restrict__ out_w1, const float* __restrict__ out_b1,
             const float* __restrict__ out_w2, const float* __restrict__ out_b2,
             const float* __restrict__ f_w1, const float* __restrict__ f_b1,
             const float* __restrict__ f_w2, const float* __restrict__ f_b2,
             float* __restrict__ out)
{
    extern __shared__ float sm[];
    float* sA  = sm + OFF_A;
    float* sC  = sm + OFF_C;
    float* sH  = sm + OFF_H;
    float* sS  = sm + OFF_S;
    float* sTF = sm + OFF_TF;
    float* sTU = sm + OFF_TU;
    float* sTR = sm + OFF_TR;
    float* sTN = sm + OFF_TN;
    float* sU  = sm + OFF_U;
    float* sP  = sm + OFF_P;

    const int tid = threadIdx.x;
    const int cta = blockIdx.x;
    const int m0  = cta * ROWS;
    const int kh  = tid >> 7;          // k-half 0/1
    const int c2  = (tid & 127) * 2;   // gemmA column base
    const int c4  = (tid & 127) * 4;   // gemmB column base

    for (int i = tid; i < 2048; i += NTHR) { sH[i] = 0.0f; sS[i] = 0.0f; }
    __syncthreads();

    ull accA[8];
    ull accB[16];
    float v[8];

    for (int t = 0; t < Tn; t++) {
        const int   obs = g_obs[t];
        const int   q   = g_qm[t];
        const float dt  = g_dt[t];

        // ---- step prologue: s -> sA[256:512]; x -> sA/sC[512:576] ----
        {
            float4 s0 = *(float4*)&sS[tid*8];
            float4 s1 = *(float4*)&sS[tid*8 + 4];
            *(float4*)&sA[(256 + tid)*8]     = s0;
            *(float4*)&sA[(256 + tid)*8 + 4] = s1;
        }
        if (tid < XDd) {
            float xv[8];
            if (obs >= 0) {
#pragma unroll
                for (int r = 0; r < 8; r++) {
                    int off = ((m0 + r)*LXn + obs)*XDd + tid;
                    xv[r] = __ldg(xd + off) * __ldg(xm + off);
                }
            } else {
#pragma unroll
                for (int r = 0; r < 8; r++) xv[r] = 0.0f;
            }
            store8(&sA[(512 + tid)*8], xv);
            store8(&sC[(512 + tid)*8], xv);
        }
        // (no sync: first consumer of these regions is S3/S5, many syncs away)

        // ---- S1: tf = tanh(h @ f_w1 + b1) ----
        gemmA(sH, kh*128, 128, f_w1 + c2, Hd, accA);
        stpA(sP, kh, c2, accA);
        __syncthreads();
        rdp(sP, tid, 0, v);
        {
            float b = __ldg(f_b1 + tid);
#pragma unroll
            for (int r = 0; r < 8; r++) v[r] = tanh_f(v[r] + b);
            store8(&sTF[tid*8], v);
        }
        __syncthreads();

        // ---- S2: hi = h + dt*(tf @ f_w2 + b2) -> sA[0:256] ----
        gemmA(sTF, kh*128, 128, f_w2 + c2, Hd, accA);
        stpA(sP, kh, c2, accA);
        __syncthreads();
        rdp(sP, tid, 0, v);
        {
            float b = __ldg(f_b2 + tid);
#pragma unroll
            for (int r = 0; r < 8; r++) v[r] = sH[tid*8 + r] + dt*(v[r] + b);
            store8(&sA[tid*8], v);
        }
        __syncthreads();

        // ---- S3: cols 0-255 tu (ug_w1), 256-511 tr (rg_w1); K=576 ----
        {
            const float* W4 = (c4 < 256) ? (ug_w1 + c4) : (rg_w1 + (c4 - 256));
            gemmB(sA, kh*288, 288, W4, Hd, accB);
            stpB(sP, kh, c4, accB);
        }
        __syncthreads();
        {
            float vu[8], vr[8];
            rdp(sP, tid, 0, vu);
            rdp(sP, tid + 256, 0, vr);
            float bu = __ldg(ug_b1 + tid), br = __ldg(rg_b1 + tid);
#pragma unroll
            for (int r = 0; r < 8; r++) {
                vu[r] = tanh_f(vu[r] + bu);
                vr[r] = tanh_f(vr[r] + br);
            }
            store8(&sTU[tid*8], vu);
            store8(&sTR[tid*8], vr);
        }
        __syncthreads();

        // ---- S4a + S4b: u-gate and r-gate outer layers, single sync ----
        gemmA(sTU, kh*128, 128, ug_w2 + c2, Hd, accA);
        stpA(sP, kh, c2, accA);
        gemmA(sTR, kh*128, 128, rg_w2 + c2, Hd, accA);
        // r-partials at column offset +256 within each half
        stpA(sP, kh, c2 + 256, accA);
        __syncthreads();
        {
            float vu[8], vr[8];
            rdp(sP, tid, 0, vu);
            rdp(sP, tid + 256, 0, vr);
            float bu = __ldg(ug_b2 + tid), br = __ldg(rg_b2 + tid);
            float uu[8], cc1[8], cc2[8];
#pragma unroll
            for (int r = 0; r < 8; r++) {
                uu[r] = sigm(vu[r] + bu);
                float rr = sigm(vr[r] + br);
                cc1[r] = sA[tid*8 + r] * rr;
                cc2[r] = sA[(256 + tid)*8 + r] * rr;
            }
            store8(&sU[tid*8], uu);
            store8(&sC[tid*8], cc1);
            store8(&sC[(256 + tid)*8], cc2);
        }
        __syncthreads();

        // ---- S5: tn = tanh(cc @ ns_w1 + b); K=576 ----
        gemmA(sC, kh*288, 288, ns_w1 + c2, Hd, accA);
        stpA(sP, kh, c2, accA);
        __syncthreads();
        rdp(sP, tid, 0, v);
        {
            float b = __ldg(ns_b1 + tid);
#pragma unroll
            for (int r = 0; r < 8; r++) v[r] = tanh_f(v[r] + b);
            store8(&sTN[tid*8], v);
        }
        __syncthreads();

        // ---- S6: ns|ns_std (N=512, ns_w2 ldw=512), gated update ----
        gemmB(sTN, kh*128, 128, ns_w2 + c4, 2*Hd, accB);
        stpB(sP, kh, c4, accB);
        __syncthreads();
        {
            float vn[8], vs[8];
            rdp(sP, tid, 0, vn);
            rdp(sP, tid + 256, 0, vs);
            float b1_ = __ldg(ns_b2 + tid), b2_ = __ldg(ns_b2 + tid + Hd);
            float hy[8], sy[8];
#pragma unroll
            for (int r = 0; r < 8; r++) {
                float u_  = sU[tid*8 + r];
                float hi_ = sA[tid*8 + r];
                float so_ = sA[(256 + tid)*8 + r];
                float ns_ = vn[r] + b1_;
                float sd_ = fabsf(vs[r] + b2_);
                hy[r] = (1.0f - u_)*ns_ + u_*hi_;
                sy[r] = fabsf((1.0f - u_)*sd_ + u_*so_);
            }
            store8(&sH[tid*8], hy);
            store8(&sS[tid*8], sy);
            if (q >= 0) {
                float* d = g_ybT + (((size_t)q*GRID + cta)*Hd + tid)*8;
                store8(d, hy);
            }
        }
        __syncthreads();
    }

    // ---- deferred out-MLP: per-CTA, 50 query states ----
    for (int q = 0; q < LYn; q++) {
        const float4* src = (const float4*)(g_ybT + ((size_t)q*GRID + cta)*Hd*8);
        float4* dstA = (float4*)sA;
        for (int i = tid; i < 512; i += NTHR) dstA[i] = src[i];
        __syncthreads();

        gemmA(sA, kh*128, 128, out_w1 + c2, Hd, accA);
        stpA(sP, kh, c2, accA);
        __syncthreads();
        rdp(sP, tid, 0, v);
        {
            float b = __ldg(out_b1 + tid);
#pragma unroll
            for (int r = 0; r < 8; r++) v[r] = tanh_f(v[r] + b);
            store8(&sTF[tid*8], v);
        }
        __syncthreads();

        if (tid < YDd) {
            gemm1f(sTF, 256, out_w2 + tid, YDd, v);
            float b = __ldg(out_b2 + tid);
#pragma unroll
            for (int r = 0; r < 8; r++)
                out[((size_t)(m0 + r)*LYn + q)*YDd + tid] = v[r] + b;
        }
        __syncthreads();
    }
}

// ---------------- launch ------------------------------------------------------
extern "C" void kernel_launch(void* const* d_in, const int* in_sizes, int n_in,
                              void* d_out, int out_size) {
    (void)in_sizes; (void)n_in; (void)out_size;
    const float* xd  = (const float*)d_in[0];
    const float* xm  = (const float*)d_in[1];
    const float* xt  = (const float*)d_in[2];
    const int*   xti = (const int*)d_in[3];
    const int*   yti = (const int*)d_in[4];

    // Unconditional (idempotent, non-stream API; no static guards allowed)
    cudaFuncSetAttribute(recur_kernel,
                         cudaFuncAttributeMaxDynamicSharedMemorySize,
                         SMEM_FLOATS * (int)sizeof(float));

    init_kernel<<<1, 256>>>(xt, xti, yti);

    recur_kernel<<<GRID, NTHR, SMEM_FLOATS * sizeof(float)>>>(
        xd, xm,
        (const float*)d_in[5],  (const float*)d_in[6],  (const float*)d_in[7],  (const float*)d_in[8],
        (const float*)d_in[9],  (const float*)d_in[10], (const float*)d_in[11], (const float*)d_in[12],
        (const float*)d_in[13], (const float*)d_in[14], (const float*)d_in[15], (const float*)d_in[16],
        (const float*)d_in[17], (const float*)d_in[18], (const float*)d_in[19], (const float*)d_in[20],
        (const float*)d_in[21], (const float*)d_in[22], (const float*)d_in[23], (const float*)d_in[24],
        (float*)d_out);
}

// round 9
// speedup vs baseline: 2.0826x; 1.0171x over previous
#include <cuda_runtime.h>
#include <math.h>

// Problem constants (fixed by the dataset)
#define Bsz 1024
#define Tn  200
#define LXn 190
#define LYn 50
#define Hd  256
#define XDd 64
#define YDd 64

#define GRID 128
#define NTHR 512
#define ROWS 8
#define PQ   4096   // floats per k-quarter partial buffer (512 cols x 8 rows)

typedef unsigned long long ull;

// ---------------- device scratch ---------------------------------------------
__device__ float g_ybT[(size_t)LYn*GRID*Hd*ROWS];   // saved new_y: [q][cta][col][8]
__device__ float g_dt[Tn];
__device__ int   g_obs[Tn];
__device__ int   g_qm [Tn];

// ---------------- packed f32x2 helpers ---------------------------------------
__device__ __forceinline__ ull fma2(ull a, ull b, ull c) {
    ull d;
    asm("fma.rn.f32x2 %0, %1, %2, %3;" : "=l"(d) : "l"(a), "l"(b), "l"(c));
    return d;
}
__device__ __forceinline__ ull dup2(float x) {
    ull d;
    asm("mov.b64 %0, {%1, %1};" : "=l"(d) : "f"(x));
    return d;
}
__device__ __forceinline__ void unpk(ull u, float& lo, float& hi) {
    asm("mov.b64 {%0, %1}, %2;" : "=f"(lo), "=f"(hi) : "l"(u));
}

__device__ __forceinline__ float sigm(float x) {
    return __fdividef(1.0f, 1.0f + __expf(-x));
}
__device__ __forceinline__ float tanh_f(float x) {
    return fmaf(2.0f, sigm(2.0f*x), -1.0f);   // |err| ~1e-6 << 1e-3 budget
}

__device__ __forceinline__ void store8(float* p, const float v[8]) {
    *(float4*)p       = make_float4(v[0], v[1], v[2], v[3]);
    *(float4*)(p + 4) = make_float4(v[4], v[5], v[6], v[7]);
}

// ---------------- GEMM cores --------------------------------------------------
// A operand in smem, layout [k][8 rows] (stride 8 floats), broadcast LDS.
// Each thread accumulates over k in [k0, k0+Kh).
//
// gemmA: 2 adjacent output columns (weights as float2).  Kh % 16 == 0.
__device__ __forceinline__ void gemmA(const float* As, int k0, int Kh,
                                      const float* __restrict__ W2, int ldw,
                                      ull acc[8])
{
#pragma unroll
    for (int i = 0; i < 8; i++) acc[i] = 0ULL;
    float2 w0[8], w1[8];
#pragma unroll
    for (int p = 0; p < 8; p++) w0[p] = __ldg((const float2*)(W2 + (size_t)(k0 + p)*ldw));

    for (int kb = k0; kb < k0 + Kh; kb += 16) {
#pragma unroll
        for (int p = 0; p < 8; p++) w1[p] = __ldg((const float2*)(W2 + (size_t)(kb + 8 + p)*ldw));
#pragma unroll
        for (int kk = 0; kk < 8; kk++) {
            const float* ap = As + (kb + kk)*8;
            ulonglong2 A0 = *(const ulonglong2*)ap;
            ulonglong2 A1 = *(const ulonglong2*)(ap + 4);
            ull wx = dup2(w0[kk].x), wy = dup2(w0[kk].y);
            acc[0] = fma2(A0.x, wx, acc[0]); acc[1] = fma2(A0.y, wx, acc[1]);
            acc[2] = fma2(A1.x, wx, acc[2]); acc[3] = fma2(A1.y, wx, acc[3]);
            acc[4] = fma2(A0.x, wy, acc[4]); acc[5] = fma2(A0.y, wy, acc[5]);
            acc[6] = fma2(A1.x, wy, acc[6]); acc[7] = fma2(A1.y, wy, acc[7]);
        }
        if (kb + 16 < k0 + Kh) {
#pragma unroll
            for (int p = 0; p < 8; p++) w0[p] = __ldg((const float2*)(W2 + (size_t)(kb + 16 + p)*ldw));
        }
#pragma unroll
        for (int kk = 0; kk < 8; kk++) {
            const float* ap = As + (kb + 8 + kk)*8;
            ulonglong2 A0 = *(const ulonglong2*)ap;
            ulonglong2 A1 = *(const ulonglong2*)(ap + 4);
            ull wx = dup2(w1[kk].x), wy = dup2(w1[kk].y);
            acc[0] = fma2(A0.x, wx, acc[0]); acc[1] = fma2(A0.y, wx, acc[1]);
            acc[2] = fma2(A1.x, wx, acc[2]); acc[3] = fma2(A1.y, wx, acc[3]);
            acc[4] = fma2(A0.x, wy, acc[4]); acc[5] = fma2(A0.y, wy, acc[5]);
            acc[6] = fma2(A1.x, wy, acc[6]); acc[7] = fma2(A1.y, wy, acc[7]);
        }
    }
}

// gemmB: 4 adjacent output columns (weights as float4).  Kh % 8 == 0.
__device__ __forceinline__ void gemmB(const float* As, int k0, int Kh,
                                      const float* __restrict__ W4, int ldw,
                                      ull acc[16])
{
#pragma unroll
    for (int i = 0; i < 16; i++) acc[i] = 0ULL;
    float4 w0[4], w1[4];
#pragma unroll
    for (int p = 0; p < 4; p++) w0[p] = __ldg((const float4*)(W4 + (size_t)(k0 + p)*ldw));

    for (int kb = k0; kb < k0 + Kh; kb += 8) {
#pragma unroll
        for (int p = 0; p < 4; p++) w1[p] = __ldg((const float4*)(W4 + (size_t)(kb + 4 + p)*ldw));
#pragma unroll
        for (int kk = 0; kk < 4; kk++) {
            const float* ap = As + (kb + kk)*8;
            ulonglong2 A0 = *(const ulonglong2*)ap;
            ulonglong2 A1 = *(const ulonglong2*)(ap + 4);
            ull wx = dup2(w0[kk].x), wy = dup2(w0[kk].y);
            ull wz = dup2(w0[kk].z), ww = dup2(w0[kk].w);
            acc[0]  = fma2(A0.x, wx, acc[0]);  acc[1]  = fma2(A0.y, wx, acc[1]);
            acc[2]  = fma2(A1.x, wx, acc[2]);  acc[3]  = fma2(A1.y, wx, acc[3]);
            acc[4]  = fma2(A0.x, wy, acc[4]);  acc[5]  = fma2(A0.y, wy, acc[5]);
            acc[6]  = fma2(A1.x, wy, acc[6]);  acc[7]  = fma2(A1.y, wy, acc[7]);
            acc[8]  = fma2(A0.x, wz, acc[8]);  acc[9]  = fma2(A0.y, wz, acc[9]);
            acc[10] = fma2(A1.x, wz, acc[10]); acc[11] = fma2(A1.y, wz, acc[11]);
            acc[12] = fma2(A0.x, ww, acc[12]); acc[13] = fma2(A0.y, ww, acc[13]);
            acc[14] = fma2(A1.x, ww, acc[14]); acc[15] = fma2(A1.y, ww, acc[15]);
        }
        if (kb + 8 < k0 + Kh) {
#pragma unroll
            for (int p = 0; p < 4; p++) w0[p] = __ldg((const float4*)(W4 + (size_t)(kb + 8 + p)*ldw));
        }
#pragma unroll
        for (int kk = 0; kk < 4; kk++) {
            const float* ap = As + (kb + 4 + kk)*8;
            ulonglong2 A0 = *(const ulonglong2*)ap;
            ulonglong2 A1 = *(const ulonglong2*)(ap + 4);
            ull wx = dup2(w1[kk].x), wy = dup2(w1[kk].y);
            ull wz = dup2(w1[kk].z), ww = dup2(w1[kk].w);
            acc[0]  = fma2(A0.x, wx, acc[0]);  acc[1]  = fma2(A0.y, wx, acc[1]);
            acc[2]  = fma2(A1.x, wx, acc[2]);  acc[3]  = fma2(A1.y, wx, acc[3]);
            acc[4]  = fma2(A0.x, wy, acc[4]);  acc[5]  = fma2(A0.y, wy, acc[5]);
            acc[6]  = fma2(A1.x, wy, acc[6]);  acc[7]  = fma2(A1.y, wy, acc[7]);
            acc[8]  = fma2(A0.x, wz, acc[8]);  acc[9]  = fma2(A0.y, wz, acc[9]);
            acc[10] = fma2(A1.x, wz, acc[10]); acc[11] = fma2(A1.y, wz, acc[11]);
            acc[12] = fma2(A0.x, ww, acc[12]); acc[13] = fma2(A0.y, ww, acc[13]);
            acc[14] = fma2(A1.x, ww, acc[14]); acc[15] = fma2(A1.y, ww, acc[15]);
        }
    }
}

// single-column full-K core (tiny O2 stage only)
__device__ __forceinline__ void gemm1f(const float* As, int K,
                                       const float* __restrict__ Wc, int ldw,
                                       float v[8])
{
    ull a0 = 0, a1 = 0, a2 = 0, a3 = 0;
    for (int k = 0; k < K; k++) {
        const float* ap = As + k*8;
        ulonglong2 A0 = *(const ulonglong2*)ap;
        ulonglong2 A1 = *(const ulonglong2*)(ap + 4);
        ull wb = dup2(__ldg(Wc + (size_t)k*ldw));
        a0 = fma2(A0.x, wb, a0); a1 = fma2(A0.y, wb, a1);
        a2 = fma2(A1.x, wb, a2); a3 = fma2(A1.y, wb, a3);
    }
    unpk(a0, v[0], v[1]); unpk(a1, v[2], v[3]);
    unpk(a2, v[4], v[5]); unpk(a3, v[6], v[7]);
}

// store gemmA partials (2 cols) into quarter kq
__device__ __forceinline__ void stpA(float* sP, int kq, int c, const ull acc[8]) {
    float v0[8], v1[8];
    unpk(acc[0], v0[0], v0[1]); unpk(acc[1], v0[2], v0[3]);
    unpk(acc[2], v0[4], v0[5]); unpk(acc[3], v0[6], v0[7]);
    unpk(acc[4], v1[0], v1[1]); unpk(acc[5], v1[2], v1[3]);
    unpk(acc[6], v1[4], v1[5]); unpk(acc[7], v1[6], v1[7]);
    store8(&sP[kq*PQ + c*8], v0);
    store8(&sP[kq*PQ + (c + 1)*8], v1);
}
// store gemmB partials (4 cols)
__device__ __forceinline__ void stpB(float* sP, int kq, int c4, const ull acc[16]) {
#pragma unroll
    for (int cc = 0; cc < 4; cc++) {
        float v[8];
        unpk(acc[cc*4 + 0], v[0], v[1]); unpk(acc[cc*4 + 1], v[2], v[3]);
        unpk(acc[cc*4 + 2], v[4], v[5]); unpk(acc[cc*4 + 3], v[6], v[7]);
        store8(&sP[kq*PQ + (c4 + cc)*8], v);
    }
}
// epilogue read: sum 4 quarter-partials for column col
__device__ __forceinline__ void rdp(const float* sP, int col, float v[8]) {
    const float* p = sP + col*8;
#pragma unroll
    for (int i = 0; i < 8; i++) v[i] = 0.0f;
#pragma unroll
    for (int q = 0; q < 4; q++) {
        float4 a0 = *(const float4*)(p + q*PQ);
        float4 a1 = *(const float4*)(p + q*PQ + 4);
        v[0] += a0.x; v[1] += a0.y; v[2] += a0.z; v[3] += a0.w;
        v[4] += a1.x; v[5] += a1.y; v[6] += a1.z; v[7] += a1.w;
    }
}

// ---------------- init: dt / obs-slot / query maps ---------------------------
__global__ void init_kernel(const float* __restrict__ x_time,
                            const int* __restrict__ x_idx,
                            const int* __restrict__ y_idx) {
    int tid = threadIdx.x;
    for (int t = tid; t < Tn; t += blockDim.x) { g_obs[t] = -1; g_qm[t] = -1; }
    __syncthreads();
    for (int i = tid; i < LXn; i += blockDim.x) g_obs[x_idx[i]] = i;
    for (int j = tid; j < LYn; j += blockDim.x) g_qm[y_idx[j]] = j;
    __syncthreads();
    for (int t = tid; t < Tn; t += blockDim.x) {
        float d;
        float tlast = x_time[Tn - 1];
        if (t == 0)      d = tlast - (tlast + 0.01f);
        else if (t == 1) d = tlast - x_time[0];
        else             d = x_time[t - 2] - x_time[t - 1];
        g_dt[t] = d;
    }
}

// ---------------- smem layout (floats) ----------------------------------------
#define OFF_A  0        // [576][8] cat(hi, s, x)
#define OFF_C  4608     // [576][8] cat(c1, c2, x)
#define OFF_H  9216     // [256][8]
#define OFF_S  11264    // [256][8]
#define OFF_TF 13312    // [256][8]
#define OFF_TU 15360    // [256][8]
#define OFF_TR 17408    // [256][8]
#define OFF_TN 19456    // [256][8]
#define OFF_U  21504    // [256][8]
#define OFF_P  23552    // [4][512][8] partials
#define SMEM_FLOATS 39936

// ---------------- persistent per-CTA recurrence -------------------------------
__global__ void __launch_bounds__(NTHR, 1)
recur_kernel(const float* __restrict__ xd, const float* __restrict__ xm,
             const float* __restrict__ ug_w1, const float* __restrict__ ug_b1,
             const float* __restrict__ ug_w2, const float* __restrict__ ug_b2,
             const float* __restrict__ rg_w1, const float* __restrict__ rg_b1,
             const float* __restrict__ rg_w2, const float* __restrict__ rg_b2,
             const float* __restrict__ ns_w1, const float* __restrict__ ns_b1,
             const float* __restrict__ ns_w2, const float* __restrict__ ns_b2,
             const float* __restrict__ out_w1, const float* __restrict__ out_b1,
             const float* __restrict__ out_w2, const float* __restrict__ out_b2,
             const float* __restrict__ f_w1, const float* __restrict__ f_b1,
             const float* __restrict__ f_w2, const float* __restrict__ f_b2,
             float* __restrict__ out)
{
    extern __shared__ float sm[];
    float* sA  = sm + OFF_A;
    float* sC  = sm + OFF_C;
    float* sH  = sm + OFF_H;
    float* sS  = sm + OFF_S;
    float* sTF = sm + OFF_TF;
    float* sTU = sm + OFF_TU;
    float* sTR = sm + OFF_TR;
    float* sTN = sm + OFF_TN;
    float* sU  = sm + OFF_U;
    float* sP  = sm + OFF_P;

    const int tid = threadIdx.x;
    const int cta = blockIdx.x;
    const int m0  = cta * ROWS;
    const int kq  = tid >> 7;          // k-quarter 0..3
    const int t2  = tid & 127;
    const int c2  = t2 * 2;            // gemmA column base
    const int c4  = t2 * 4;            // gemmB column base

    for (int i = tid; i < 2048; i += NTHR) { sH[i] = 0.0f; sS[i] = 0.0f; }
    __syncthreads();

    ull accA[8];
    ull accB[16];
    float v[8];

    for (int t = 0; t < Tn; t++) {
        const int   obs = g_obs[t];
        const int   q   = g_qm[t];
        const float dt  = g_dt[t];

        // ---- step prologue: s -> sA[256:512]; x -> sA/sC[512:576] ----
        if (tid < 256) {
            float4 s0 = *(float4*)&sS[tid*8];
            float4 s1 = *(float4*)&sS[tid*8 + 4];
            *(float4*)&sA[(256 + tid)*8]     = s0;
            *(float4*)&sA[(256 + tid)*8 + 4] = s1;
        }
        if (tid < XDd) {
            float xv[8];
            if (obs >= 0) {
#pragma unroll
                for (int r = 0; r < 8; r++) {
                    int off = ((m0 + r)*LXn + obs)*XDd + tid;
                    xv[r] = __ldg(xd + off) * __ldg(xm + off);
                }
            } else {
#pragma unroll
                for (int r = 0; r < 8; r++) xv[r] = 0.0f;
            }
            store8(&sA[(512 + tid)*8], xv);
            store8(&sC[(512 + tid)*8], xv);
        }
        // (first consumer of these regions is S3/S5 — syncs in between)

        // ---- S1: tf = tanh(h @ f_w1 + b1)  [K=256, quarter=64] ----
        gemmA(sH, kq*64, 64, f_w1 + c2, Hd, accA);
        stpA(sP, kq, c2, accA);
        __syncthreads();
        if (tid < 256) {
            rdp(sP, tid, v);
            float b = __ldg(f_b1 + tid);
#pragma unroll
            for (int r = 0; r < 8; r++) v[r] = tanh_f(v[r] + b);
            store8(&sTF[tid*8], v);
        }
        __syncthreads();

        // ---- S2: hi = h + dt*(tf @ f_w2 + b2) -> sA[0:256] ----
        gemmA(sTF, kq*64, 64, f_w2 + c2, Hd, accA);
        stpA(sP, kq, c2, accA);
        __syncthreads();
        if (tid < 256) {
            rdp(sP, tid, v);
            float b = __ldg(f_b2 + tid);
#pragma unroll
            for (int r = 0; r < 8; r++) v[r] = sH[tid*8 + r] + dt*(v[r] + b);
            store8(&sA[tid*8], v);
        }
        __syncthreads();

        // ---- S3: cols 0-255 tu (ug_w1), 256-511 tr (rg_w1); K=576, q=144 ----
        {
            const float* W4 = (c4 < 256) ? (ug_w1 + c4) : (rg_w1 + (c4 - 256));
            gemmB(sA, kq*144, 144, W4, Hd, accB);
            stpB(sP, kq, c4, accB);
        }
        __syncthreads();
        if (tid < 256) {
            float vu[8], vr[8];
            rdp(sP, tid, vu);
            rdp(sP, tid + 256, vr);
            float bu = __ldg(ug_b1 + tid), br = __ldg(rg_b1 + tid);
#pragma unroll
            for (int r = 0; r < 8; r++) {
                vu[r] = tanh_f(vu[r] + bu);
                vr[r] = tanh_f(vr[r] + br);
            }
            store8(&sTU[tid*8], vu);
            store8(&sTR[tid*8], vr);
        }
        __syncthreads();

        // ---- S4a + S4b: u-gate and r-gate outer layers, single sync ----
        gemmA(sTU, kq*64, 64, ug_w2 + c2, Hd, accA);
        stpA(sP, kq, c2, accA);
        gemmA(sTR, kq*64, 64, rg_w2 + c2, Hd, accA);
        stpA(sP, kq, c2 + 256, accA);
        __syncthreads();
        if (tid < 256) {
            float vu[8], vr[8];
            rdp(sP, tid, vu);
            rdp(sP, tid + 256, vr);
            float bu = __ldg(ug_b2 + tid), br = __ldg(rg_b2 + tid);
            float uu[8], cc1[8], cc2[8];
#pragma unroll
            for (int r = 0; r < 8; r++) {
                uu[r] = sigm(vu[r] + bu);
                float rr = sigm(vr[r] + br);
                cc1[r] = sA[tid*8 + r] * rr;
                cc2[r] = sA[(256 + tid)*8 + r] * rr;
            }
            store8(&sU[tid*8], uu);
            store8(&sC[tid*8], cc1);
            store8(&sC[(256 + tid)*8], cc2);
        }
        __syncthreads();

        // ---- S5: tn = tanh(cc @ ns_w1 + b); K=576, quarter=144 ----
        gemmA(sC, kq*144, 144, ns_w1 + c2, Hd, accA);
        stpA(sP, kq, c2, accA);
        __syncthreads();
        if (tid < 256) {
            rdp(sP, tid, v);
            float b = __ldg(ns_b1 + tid);
#pragma unroll
            for (int r = 0; r < 8; r++) v[r] = tanh_f(v[r] + b);
            store8(&sTN[tid*8], v);
        }
        __syncthreads();

        // ---- S6: ns|ns_std (N=512, ns_w2 ldw=512), gated update ----
        gemmB(sTN, kq*64, 64, ns_w2 + c4, 2*Hd, accB);
        stpB(sP, kq, c4, accB);
        __syncthreads();
        if (tid < 256) {
            float vn[8], vs[8];
            rdp(sP, tid, vn);
            rdp(sP, tid + 256, vs);
            float b1_ = __ldg(ns_b2 + tid), b2_ = __ldg(ns_b2 + tid + Hd);
            float hy[8], sy[8];
#pragma unroll
            for (int r = 0; r < 8; r++) {
                float u_  = sU[tid*8 + r];
                float hi_ = sA[tid*8 + r];
                float so_ = sA[(256 + tid)*8 + r];
                float ns_ = vn[r] + b1_;
                float sd_ = fabsf(vs[r] + b2_);
                hy[r] = (1.0f - u_)*ns_ + u_*hi_;
                sy[r] = fabsf((1.0f - u_)*sd_ + u_*so_);
            }
            store8(&sH[tid*8], hy);
            store8(&sS[tid*8], sy);
            if (q >= 0) {
                float* d = g_ybT + (((size_t)q*GRID + cta)*Hd + tid)*8;
                store8(d, hy);
            }
        }
        __syncthreads();
    }

    // ---- deferred out-MLP: per-CTA, 50 query states ----
    for (int q = 0; q < LYn; q++) {
        const float4* src = (const float4*)(g_ybT + ((size_t)q*GRID + cta)*Hd*8);
        float4* dstA = (float4*)sA;
        for (int i = tid; i < 512; i += NTHR) dstA[i] = src[i];
        __syncthreads();

        gemmA(sA, kq*64, 64, out_w1 + c2, Hd, accA);
        stpA(sP, kq, c2, accA);
        __syncthreads();
        if (tid < 256) {
            rdp(sP, tid, v);
            float b = __ldg(out_b1 + tid);
#pragma unroll
            for (int r = 0; r < 8; r++) v[r] = tanh_f(v[r] + b);
            store8(&sTF[tid*8], v);
        }
        __syncthreads();

        if (tid < YDd) {
            gemm1f(sTF, 256, out_w2 + tid, YDd, v);
            float b = __ldg(out_b2 + tid);
#pragma unroll
            for (int r = 0; r < 8; r++)
                out[((size_t)(m0 + r)*LYn + q)*YDd + tid] = v[r] + b;
        }
        __syncthreads();
    }
}

// ---------------- launch ------------------------------------------------------
extern "C" void kernel_launch(void* const* d_in, const int* in_sizes, int n_in,
                              void* d_out, int out_size) {
    (void)in_sizes; (void)n_in; (void)out_size;
    const float* xd  = (const float*)d_in[0];
    const float* xm  = (const float*)d_in[1];
    const float* xt  = (const float*)d_in[2];
    const int*   xti = (const int*)d_in[3];
    const int*   yti = (const int*)d_in[4];

    // Unconditional (idempotent, non-stream API; no static guards allowed)
    cudaFuncSetAttribute(recur_kernel,
                         cudaFuncAttributeMaxDynamicSharedMemorySize,
                         SMEM_FLOATS * (int)sizeof(float));

    init_kernel<<<1, 256>>>(xt, xti, yti);

    recur_kernel<<<GRID, NTHR, SMEM_FLOATS * sizeof(float)>>>(
        xd, xm,
        (const float*)d_in[5],  (const float*)d_in[6],  (const float*)d_in[7],  (const float*)d_in[8],
        (const float*)d_in[9],  (const float*)d_in[10], (const float*)d_in[11], (const float*)d_in[12],
        (const float*)d_in[13], (const float*)d_in[14], (const float*)d_in[15], (const float*)d_in[16],
        (const float*)d_in[17], (const float*)d_in[18], (const float*)d_in[19], (const float*)d_in[20],
        (const float*)d_in[21], (const float*)d_in[22], (const float*)d_in[23], (const float*)d_in[24],
        (float*)d_out);
}

// round 10
// speedup vs baseline: 2.3320x; 1.1198x over previous
#include <cuda_runtime.h>
#include <math.h>

// Problem constants (fixed by the dataset)
#define Bsz 1024
#define Tn  200
#define LXn 190
#define LYn 50
#define Hd  256
#define XDd 64
#define YDd 64

#define GRID 128
#define NTHR 512
#define ROWS 8

typedef unsigned long long ull;

// ---------------- device scratch ---------------------------------------------
__device__ float g_ybT[(size_t)LYn*GRID*Hd*ROWS];   // saved new_y: [q][cta][col][8]
__device__ float g_dt[Tn];
__device__ int   g_obs[Tn];
__device__ int   g_qm [Tn];

// ---------------- packed f32x2 helpers ---------------------------------------
__device__ __forceinline__ ull fma2(ull a, ull b, ull c) {
    ull d;
    asm("fma.rn.f32x2 %0, %1, %2, %3;" : "=l"(d) : "l"(a), "l"(b), "l"(c));
    return d;
}
__device__ __forceinline__ ull dup2(float x) {
    ull d;
    asm("mov.b64 %0, {%1, %1};" : "=l"(d) : "f"(x));
    return d;
}
__device__ __forceinline__ void unpk(ull u, float& lo, float& hi) {
    asm("mov.b64 {%0, %1}, %2;" : "=f"(lo), "=f"(hi) : "l"(u));
}

__device__ __forceinline__ float sigm(float x) {
    return __fdividef(1.0f, 1.0f + __expf(-x));
}
__device__ __forceinline__ float tanh_f(float x) {
    return fmaf(2.0f, sigm(2.0f*x), -1.0f);   // |err| ~1e-6 << 1e-3 budget
}

// ---------------- GEMM core ----------------------------------------------------
// A operand in smem, layout [k][8 rows] (stride 8 floats), broadcast LDS.
// Thread computes 2 strips x 4 cols x 8 rows over k in [k0, k0+Kh).
// acc[strip*16 + c*4 + rp] packs rows (2rp, 2rp+1) of column c.
template<bool DUAL>
__device__ __forceinline__ void gemm8(const float* AsA, const float* AsB,
                                      int k0, int Kh,
                                      const float* __restrict__ WA, int ldwA,
                                      const float* __restrict__ WB, int ldwB,
                                      ull acc[32])
{
#pragma unroll
    for (int i = 0; i < 32; i++) acc[i] = 0ULL;
#pragma unroll 4
    for (int k = k0; k < k0 + Kh; k++) {
        const float* ap = AsA + k*8;
        ulonglong2 A0 = *(const ulonglong2*)ap;
        ulonglong2 A1 = *(const ulonglong2*)(ap + 4);
        ulonglong2 B0, B1;
        if (DUAL) {
            const float* bp = AsB + k*8;
            B0 = *(const ulonglong2*)bp;
            B1 = *(const ulonglong2*)(bp + 4);
        } else {
            B0 = A0; B1 = A1;
        }
        float4 wa = __ldg((const float4*)(WA + (size_t)k*ldwA));
        float4 wb = __ldg((const float4*)(WB + (size_t)k*ldwB));
        ull w;
        w = dup2(wa.x);
        acc[0]  = fma2(A0.x, w, acc[0]);  acc[1]  = fma2(A0.y, w, acc[1]);
        acc[2]  = fma2(A1.x, w, acc[2]);  acc[3]  = fma2(A1.y, w, acc[3]);
        w = dup2(wa.y);
        acc[4]  = fma2(A0.x, w, acc[4]);  acc[5]  = fma2(A0.y, w, acc[5]);
        acc[6]  = fma2(A1.x, w, acc[6]);  acc[7]  = fma2(A1.y, w, acc[7]);
        w = dup2(wa.z);
        acc[8]  = fma2(A0.x, w, acc[8]);  acc[9]  = fma2(A0.y, w, acc[9]);
        acc[10] = fma2(A1.x, w, acc[10]); acc[11] = fma2(A1.y, w, acc[11]);
        w = dup2(wa.w);
        acc[12] = fma2(A0.x, w, acc[12]); acc[13] = fma2(A0.y, w, acc[13]);
        acc[14] = fma2(A1.x, w, acc[14]); acc[15] = fma2(A1.y, w, acc[15]);
        w = dup2(wb.x);
        acc[16] = fma2(B0.x, w, acc[16]); acc[17] = fma2(B0.y, w, acc[17]);
        acc[18] = fma2(B1.x, w, acc[18]); acc[19] = fma2(B1.y, w, acc[19]);
        w = dup2(wb.y);
        acc[20] = fma2(B0.x, w, acc[20]); acc[21] = fma2(B0.y, w, acc[21]);
        acc[22] = fma2(B1.x, w, acc[22]); acc[23] = fma2(B1.y, w, acc[23]);
        w = dup2(wb.z);
        acc[24] = fma2(B0.x, w, acc[24]); acc[25] = fma2(B0.y, w, acc[25]);
        acc[26] = fma2(B1.x, w, acc[26]); acc[27] = fma2(B1.y, w, acc[27]);
        w = dup2(wb.w);
        acc[28] = fma2(B0.x, w, acc[28]); acc[29] = fma2(B0.y, w, acc[29]);
        acc[30] = fma2(B1.x, w, acc[30]); acc[31] = fma2(B1.y, w, acc[31]);
    }
}

// Store partials row-major: sP[base + r*rowStride + col]; lane-contiguous STS.128.
__device__ __forceinline__ void stp8(float* sP, int rowStride, int base,
                                     int cA, int cB, const ull acc[32])
{
#pragma unroll
    for (int rp = 0; rp < 4; rp++) {
        float4 rA0, rA1, rB0, rB1;
        unpk(acc[0*4 + rp],  rA0.x, rA1.x);
        unpk(acc[1*4 + rp],  rA0.y, rA1.y);
        unpk(acc[2*4 + rp],  rA0.z, rA1.z);
        unpk(acc[3*4 + rp],  rA0.w, rA1.w);
        unpk(acc[16 + 0*4 + rp], rB0.x, rB1.x);
        unpk(acc[16 + 1*4 + rp], rB0.y, rB1.y);
        unpk(acc[16 + 2*4 + rp], rB0.z, rB1.z);
        unpk(acc[16 + 3*4 + rp], rB0.w, rB1.w);
        *(float4*)(sP + base + (2*rp)*rowStride + cA)     = rA0;
        *(float4*)(sP + base + (2*rp + 1)*rowStride + cA) = rA1;
        *(float4*)(sP + base + (2*rp)*rowStride + cB)     = rB0;
        *(float4*)(sP + base + (2*rp + 1)*rowStride + cB) = rB1;
    }
}

// Sum nsplit partials for 4 rows (rh*4..rh*4+3) of column col.
template<int NSPLIT>
__device__ __forceinline__ void rde(const float* sP, int rowStride,
                                    int col, int rh, float v[4])
{
    v[0] = v[1] = v[2] = v[3] = 0.0f;
#pragma unroll
    for (int ks = 0; ks < NSPLIT; ks++) {
        const float* p = sP + ks*8*rowStride + rh*4*rowStride + col;
        v[0] += p[0];
        v[1] += p[rowStride];
        v[2] += p[2*rowStride];
        v[3] += p[3*rowStride];
    }
}

// single-column full-K core (tiny O2 stage only)
__device__ __forceinline__ void gemm1f(const float* As, int K,
                                       const float* __restrict__ Wc, int ldw,
                                       float v[8])
{
    ull a0 = 0, a1 = 0, a2 = 0, a3 = 0;
    for (int k = 0; k < K; k++) {
        const float* ap = As + k*8;
        ulonglong2 A0 = *(const ulonglong2*)ap;
        ulonglong2 A1 = *(const ulonglong2*)(ap + 4);
        ull wb = dup2(__ldg(Wc + (size_t)k*ldw));
        a0 = fma2(A0.x, wb, a0); a1 = fma2(A0.y, wb, a1);
        a2 = fma2(A1.x, wb, a2); a3 = fma2(A1.y, wb, a3);
    }
    unpk(a0, v[0], v[1]); unpk(a1, v[2], v[3]);
    unpk(a2, v[4], v[5]); unpk(a3, v[6], v[7]);
}

// ---------------- init: dt / obs-slot / query maps ---------------------------
__global__ void init_kernel(const float* __restrict__ x_time,
                            const int* __restrict__ x_idx,
                            const int* __restrict__ y_idx) {
    int tid = threadIdx.x;
    for (int t = tid; t < Tn; t += blockDim.x) { g_obs[t] = -1; g_qm[t] = -1; }
    __syncthreads();
    for (int i = tid; i < LXn; i += blockDim.x) g_obs[x_idx[i]] = i;
    for (int j = tid; j < LYn; j += blockDim.x) g_qm[y_idx[j]] = j;
    __syncthreads();
    for (int t = tid; t < Tn; t += blockDim.x) {
        float d;
        float tlast = x_time[Tn - 1];
        if (t == 0)      d = tlast - (tlast + 0.01f);
        else if (t == 1) d = tlast - x_time[0];
        else             d = x_time[t - 2] - x_time[t - 1];
        g_dt[t] = d;
    }
}

// ---------------- smem layout (floats) ----------------------------------------
#define OFF_A  0        // [576][8] cat(hi, s, x)
#define OFF_C  4608     // [576][8] cat(c1, c2, x)
#define OFF_H  9216     // [256][8]
#define OFF_S  11264    // [256][8]
#define OFF_TF 13312    // [256][8]
#define OFF_TU 15360    // [256][8]
#define OFF_TR 17408    // [256][8]
#define OFF_TN 19456    // [256][8]
#define OFF_U  21504    // [256][8]
#define OFF_P  23552    // partials: up to 16 slices x 8 rows x 256 cols (row-major)
#define SMEM_FLOATS 56320   // 225,280 bytes

// ---------------- persistent per-CTA recurrence -------------------------------
__global__ void __launch_bounds__(NTHR, 1)
recur_kernel(const float* __restrict__ xd, const float* __restrict__ xm,
             const float* __restrict__ ug_w1, const float* __restrict__ ug_b1,
             const float* __restrict__ ug_w2, const float* __restrict__ ug_b2,
             const float* __restrict__ rg_w1, const float* __restrict__ rg_b1,
             const float* __restrict__ rg_w2, const float* __restrict__ rg_b2,
             const float* __restrict__ ns_w1, const float* __restrict__ ns_b1,
             const float* __restrict__ ns_w2, const float* __restrict__ ns_b2,
             const float* __restrict__ out_w1, const float* __restrict__ out_b1,
             const float* __restrict__ out_w2, const float* __restrict__ out_b2,
             const float* __restrict__ f_w1, const float* __restrict__ f_b1,
             const float* __restrict__ f_w2, const float* __restrict__ f_b2,
             float* __restrict__ out)
{
    extern __shared__ float sm[];
    float* sA  = sm + OFF_A;
    float* sC  = sm + OFF_C;
    float* sH  = sm + OFF_H;
    float* sS  = sm + OFF_S;
    float* sTF = sm + OFF_TF;
    float* sTU = sm + OFF_TU;
    float* sTR = sm + OFF_TR;
    float* sTN = sm + OFF_TN;
    float* sU  = sm + OFF_U;
    float* sP  = sm + OFF_P;

    const int tid = threadIdx.x;
    const int cta = blockIdx.x;
    const int m0  = cta * ROWS;

    // N=256 stage mapping: lane 0..31 covers 256 cols in 2 strips, 16 k-slices
    const int kq16 = tid >> 5;
    const int cAn  = (tid & 31) * 4;
    const int cBn  = 128 + cAn;
    // N=512 stage mapping: lane6 0..63 covers 512 cols in 2 strips, 8 k-slices
    const int kq8  = tid >> 6;
    const int cA6  = (tid & 63) * 4;
    // epilogue mapping
    const int ecol = tid & 255;
    const int erh  = tid >> 8;       // 0/1 -> rows 0-3 / 4-7

    for (int i = tid; i < 2048; i += NTHR) { sH[i] = 0.0f; sS[i] = 0.0f; }
    __syncthreads();

    ull acc[32];
    float v[4];

    for (int t = 0; t < Tn; t++) {
        const int   obs = g_obs[t];
        const int   q   = g_qm[t];
        const float dt  = g_dt[t];

        // ---- step prologue: s -> sA[256:512]; x -> sA/sC[512:576] ----
        if (tid < 256) {
            float4 s0 = *(float4*)&sS[tid*8];
            float4 s1 = *(float4*)&sS[tid*8 + 4];
            *(float4*)&sA[(256 + tid)*8]     = s0;
            *(float4*)&sA[(256 + tid)*8 + 4] = s1;
        }
        if (tid < XDd) {
            float xv[8];
            if (obs >= 0) {
#pragma unroll
                for (int r = 0; r < 8; r++) {
                    int off = ((m0 + r)*LXn + obs)*XDd + tid;
                    xv[r] = __ldg(xd + off) * __ldg(xm + off);
                }
            } else {
#pragma unroll
                for (int r = 0; r < 8; r++) xv[r] = 0.0f;
            }
            *(float4*)&sA[(512 + tid)*8]     = make_float4(xv[0], xv[1], xv[2], xv[3]);
            *(float4*)&sA[(512 + tid)*8 + 4] = make_float4(xv[4], xv[5], xv[6], xv[7]);
            *(float4*)&sC[(512 + tid)*8]     = make_float4(xv[0], xv[1], xv[2], xv[3]);
            *(float4*)&sC[(512 + tid)*8 + 4] = make_float4(xv[4], xv[5], xv[6], xv[7]);
        }
        // (first consumer of these regions is S3/S5 — syncs in between)

        // ---- S1: tf = tanh(h @ f_w1 + b1)  [N=256, K=256, 16 slices x 16] ----
        gemm8<false>(sH, sH, kq16*16, 16, f_w1 + cAn, Hd, f_w1 + cBn, Hd, acc);
        stp8(sP, 256, kq16*2048, cAn, cBn, acc);
        __syncthreads();
        {
            rde<16>(sP, 256, ecol, erh, v);
            float b = __ldg(f_b1 + ecol);
            float4 o = make_float4(tanh_f(v[0]+b), tanh_f(v[1]+b),
                                   tanh_f(v[2]+b), tanh_f(v[3]+b));
            *(float4*)(sTF + ecol*8 + erh*4) = o;
        }
        __syncthreads();

        // ---- S2: hi = h + dt*(tf @ f_w2 + b2) -> sA[0:256] ----
        gemm8<false>(sTF, sTF, kq16*16, 16, f_w2 + cAn, Hd, f_w2 + cBn, Hd, acc);
        stp8(sP, 256, kq16*2048, cAn, cBn, acc);
        __syncthreads();
        {
            rde<16>(sP, 256, ecol, erh, v);
            float b = __ldg(f_b2 + ecol);
            float4 h = *(float4*)(sH + ecol*8 + erh*4);
            float4 o = make_float4(h.x + dt*(v[0]+b), h.y + dt*(v[1]+b),
                                   h.z + dt*(v[2]+b), h.w + dt*(v[3]+b));
            *(float4*)(sA + ecol*8 + erh*4) = o;
        }
        __syncthreads();

        // ---- S3: N=512 (tu | tr), K=576, 8 slices x 72 ----
        gemm8<false>(sA, sA, kq8*72, 72, ug_w1 + cA6, Hd, rg_w1 + cA6, Hd, acc);
        stp8(sP, 512, kq8*4096, cA6, 256 + cA6, acc);
        __syncthreads();
        {
            float vu[4], vr[4];
            rde<8>(sP, 512, ecol, erh, vu);
            rde<8>(sP, 512, ecol + 256, erh, vr);
            float bu = __ldg(ug_b1 + ecol), br = __ldg(rg_b1 + ecol);
            *(float4*)(sTU + ecol*8 + erh*4) =
                make_float4(tanh_f(vu[0]+bu), tanh_f(vu[1]+bu),
                            tanh_f(vu[2]+bu), tanh_f(vu[3]+bu));
            *(float4*)(sTR + ecol*8 + erh*4) =
                make_float4(tanh_f(vr[0]+br), tanh_f(vr[1]+br),
                            tanh_f(vr[2]+br), tanh_f(vr[3]+br));
        }
        __syncthreads();

        // ---- S4: fused u/r outer layers (dual-A N=512), K=256, 8 x 32 ----
        gemm8<true>(sTU, sTR, kq8*32, 32, ug_w2 + cA6, Hd, rg_w2 + cA6, Hd, acc);
        stp8(sP, 512, kq8*4096, cA6, 256 + cA6, acc);
        __syncthreads();
        {
            float vu[4], vr[4];
            rde<8>(sP, 512, ecol, erh, vu);
            rde<8>(sP, 512, ecol + 256, erh, vr);
            float bu = __ldg(ug_b2 + ecol), br = __ldg(rg_b2 + ecol);
            float4 hi = *(float4*)(sA + ecol*8 + erh*4);
            float4 so = *(float4*)(sA + (256 + ecol)*8 + erh*4);
            float4 uu, c1, c2;
            uu.x = sigm(vu[0]+bu); uu.y = sigm(vu[1]+bu);
            uu.z = sigm(vu[2]+bu); uu.w = sigm(vu[3]+bu);
            float r0 = sigm(vr[0]+br), r1 = sigm(vr[1]+br);
            float r2 = sigm(vr[2]+br), r3 = sigm(vr[3]+br);
            c1 = make_float4(hi.x*r0, hi.y*r1, hi.z*r2, hi.w*r3);
            c2 = make_float4(so.x*r0, so.y*r1, so.z*r2, so.w*r3);
            *(float4*)(sU + ecol*8 + erh*4) = uu;
            *(float4*)(sC + ecol*8 + erh*4) = c1;
            *(float4*)(sC + (256 + ecol)*8 + erh*4) = c2;
        }
        __syncthreads();

        // ---- S5: tn = tanh(cc @ ns_w1 + b); N=256, K=576, 16 x 36 ----
        gemm8<false>(sC, sC, kq16*36, 36, ns_w1 + cAn, Hd, ns_w1 + cBn, Hd, acc);
        stp8(sP, 256, kq16*2048, cAn, cBn, acc);
        __syncthreads();
        {
            rde<16>(sP, 256, ecol, erh, v);
            float b = __ldg(ns_b1 + ecol);
            *(float4*)(sTN + ecol*8 + erh*4) =
                make_float4(tanh_f(v[0]+b), tanh_f(v[1]+b),
                            tanh_f(v[2]+b), tanh_f(v[3]+b));
        }
        __syncthreads();

        // ---- S6: ns|std (N=512, ldw=512), K=256, 8 x 32; gated update ----
        gemm8<false>(sTN, sTN, kq8*32, 32, ns_w2 + cA6, 2*Hd, ns_w2 + 256 + cA6, 2*Hd, acc);
        stp8(sP, 512, kq8*4096, cA6, 256 + cA6, acc);
        __syncthreads();
        {
            float vn[4], vs[4];
            rde<8>(sP, 512, ecol, erh, vn);
            rde<8>(sP, 512, ecol + 256, erh, vs);
            float b1_ = __ldg(ns_b2 + ecol), b2_ = __ldg(ns_b2 + ecol + Hd);
            float4 uu = *(float4*)(sU + ecol*8 + erh*4);
            float4 hi = *(float4*)(sA + ecol*8 + erh*4);
            float4 so = *(float4*)(sA + (256 + ecol)*8 + erh*4);
            float4 hy, sy;
            {
                float ns0 = vn[0]+b1_, sd0 = fabsf(vs[0]+b2_);
                float ns1 = vn[1]+b1_, sd1 = fabsf(vs[1]+b2_);
                float ns2 = vn[2]+b1_, sd2 = fabsf(vs[2]+b2_);
                float ns3 = vn[3]+b1_, sd3 = fabsf(vs[3]+b2_);
                hy = make_float4((1.0f-uu.x)*ns0 + uu.x*hi.x,
                                 (1.0f-uu.y)*ns1 + uu.y*hi.y,
                                 (1.0f-uu.z)*ns2 + uu.z*hi.z,
                                 (1.0f-uu.w)*ns3 + uu.w*hi.w);
                sy = make_float4(fabsf((1.0f-uu.x)*sd0 + uu.x*so.x),
                                 fabsf((1.0f-uu.y)*sd1 + uu.y*so.y),
                                 fabsf((1.0f-uu.z)*sd2 + uu.z*so.z),
                                 fabsf((1.0f-uu.w)*sd3 + uu.w*so.w));
            }
            *(float4*)(sH + ecol*8 + erh*4) = hy;
            *(float4*)(sS + ecol*8 + erh*4) = sy;
            if (q >= 0) {
                float* d = g_ybT + (((size_t)q*GRID + cta)*Hd + ecol)*8 + erh*4;
                *(float4*)d = hy;
            }
        }
        __syncthreads();
    }

    // ---- deferred out-MLP: per-CTA, 50 query states ----
    for (int q = 0; q < LYn; q++) {
        const float4* src = (const float4*)(g_ybT + ((size_t)q*GRID + cta)*Hd*8);
        float4* dstA = (float4*)sA;
        for (int i = tid; i < 512; i += NTHR) dstA[i] = src[i];
        __syncthreads();

        gemm8<false>(sA, sA, kq16*16, 16, out_w1 + cAn, Hd, out_w1 + cBn, Hd, acc);
        stp8(sP, 256, kq16*2048, cAn, cBn, acc);
        __syncthreads();
        {
            rde<16>(sP, 256, ecol, erh, v);
            float b = __ldg(out_b1 + ecol);
            *(float4*)(sTF + ecol*8 + erh*4) =
                make_float4(tanh_f(v[0]+b), tanh_f(v[1]+b),
                            tanh_f(v[2]+b), tanh_f(v[3]+b));
        }
        __syncthreads();

        if (tid < YDd) {
            float o[8];
            gemm1f(sTF, 256, out_w2 + tid, YDd, o);
            float b = __ldg(out_b2 + tid);
#pragma unroll
            for (int r = 0; r < 8; r++)
                out[((size_t)(m0 + r)*LYn + q)*YDd + tid] = o[r] + b;
        }
        __syncthreads();
    }
}

// ---------------- launch ------------------------------------------------------
extern "C" void kernel_launch(void* const* d_in, const int* in_sizes, int n_in,
                              void* d_out, int out_size) {
    (void)in_sizes; (void)n_in; (void)out_size;
    const float* xd  = (const float*)d_in[0];
    const float* xm  = (const float*)d_in[1];
    const float* xt  = (const float*)d_in[2];
    const int*   xti = (const int*)d_in[3];
    const int*   yti = (const int*)d_in[4];

    // Unconditional (idempotent, non-stream API; no static guards allowed)
    cudaFuncSetAttribute(recur_kernel,
                         cudaFuncAttributeMaxDynamicSharedMemorySize,
                         SMEM_FLOATS * (int)sizeof(float));

    init_kernel<<<1, 256>>>(xt, xti, yti);

    recur_kernel<<<GRID, NTHR, SMEM_FLOATS * sizeof(float)>>>(
        xd, xm,
        (const float*)d_in[5],  (const float*)d_in[6],  (const float*)d_in[7],  (const float*)d_in[8],
        (const float*)d_in[9],  (const float*)d_in[10], (const float*)d_in[11], (const float*)d_in[12],
        (const float*)d_in[13], (const float*)d_in[14], (const float*)d_in[15], (const float*)d_in[16],
        (const float*)d_in[17], (const float*)d_in[18], (const float*)d_in[19], (const float*)d_in[20],
        (const float*)d_in[21], (const float*)d_in[22], (const float*)d_in[23], (const float*)d_in[24],
        (float*)d_out);
}